// round 12
// baseline (speedup 1.0000x reference)
#include <cuda_runtime.h>
#include <cuda_bf16.h>
#include <cstdint>

#define BH        64
#define SEQ       1024
#define DH        64
#define ROWS      16
#define NTHREADS  256
#define KTILE     128
#define NTILES    8
#define QROWB     144               // Q smem row bytes (64 bf16 + pad)
#define SZ_KH     16384             // K hi sub-buffer (128 rows x 128B, swizzled)
#define SZ_VH     16384             // V hi sub-buffer (64 rows x 256B, swizzled)

// smem byte offsets (no P buffer -> 2 CTAs/SM)
#define OFF_K    0                  // K hi 16K | lo 16K
#define OFF_V    32768              // V hi 16K | lo 16K
#define OFF_QH   65536
#define SZ_QROW  (ROWS * QROWB)     // 2304
#define OFF_QL   (OFF_QH + SZ_QROW) // 67840
#define OFF_PAD  (OFF_QL + SZ_QROW) // 70144
#define OFF_L    (OFF_PAD + SEQ*4)  // 74240
#define OFF_C    (OFF_L + ROWS*4)   // 74304
#define OFF_FLG  (OFF_C + ROWS*4)   // 74368
#define OFF_MB   (OFF_FLG + 16)     // 74384: mbK,mbV,eK,eV (8B each)
#define SMEM_BYTES (OFF_MB + 32)    // 74416 (x2 = 148832 <= 227KB)

__device__ __nv_bfloat16 g_kh[(size_t)BH * SEQ * DH];   // tile-contig, swizzled
__device__ __nv_bfloat16 g_kl[(size_t)BH * SEQ * DH];
__device__ __nv_bfloat16 g_vth[(size_t)BH * NTILES * DH * KTILE];  // [bh][t][d][s]
__device__ __nv_bfloat16 g_vtl[(size_t)BH * NTILES * DH * KTILE];
__device__ float g_scratch[(size_t)BH * SEQ * SEQ];

// ---------------------------------------------------------------------------
__device__ __forceinline__ uint32_t packsplit(float x, float y, uint32_t& lo) {
    __nv_bfloat16 hx = __float2bfloat16_rn(x);
    __nv_bfloat16 hy = __float2bfloat16_rn(y);
    __nv_bfloat16 lx = __float2bfloat16_rn(x - __bfloat162float(hx));
    __nv_bfloat16 ly = __float2bfloat16_rn(y - __bfloat162float(hy));
    lo = (uint32_t)__bfloat16_as_ushort(lx) | ((uint32_t)__bfloat16_as_ushort(ly) << 16);
    return (uint32_t)__bfloat16_as_ushort(hx) | ((uint32_t)__bfloat16_as_ushort(hy) << 16);
}

__device__ __forceinline__ void mma16816(float* c, const uint32_t* a,
                                         uint32_t b0, uint32_t b1) {
    asm volatile(
        "mma.sync.aligned.m16n8k16.row.col.f32.bf16.bf16.f32 "
        "{%0,%1,%2,%3},{%4,%5,%6,%7},{%8,%9},{%0,%1,%2,%3};"
        : "+f"(c[0]), "+f"(c[1]), "+f"(c[2]), "+f"(c[3])
        : "r"(a[0]), "r"(a[1]), "r"(a[2]), "r"(a[3]), "r"(b0), "r"(b1));
}

__device__ __forceinline__ void ldsm4(uint32_t* r, uint32_t addr) {
    asm volatile("ldmatrix.sync.aligned.m8n8.x4.shared.b16 {%0,%1,%2,%3},[%4];"
                 : "=r"(r[0]), "=r"(r[1]), "=r"(r[2]), "=r"(r[3]) : "r"(addr));
}
__device__ __forceinline__ void ldsm2(uint32_t& r0, uint32_t& r1, uint32_t addr) {
    asm volatile("ldmatrix.sync.aligned.m8n8.x2.shared.b16 {%0,%1},[%2];"
                 : "=r"(r0), "=r"(r1) : "r"(addr));
}

__device__ __forceinline__ float epival(float s, int col, int qrow, const int* pads) {
    bool m = (pads[col] != 0) || (col > qrow);
    return m ? 0.f : __expf(s * 0.125f);
}

// ---- mbarrier / cluster helpers ---------------------------------------------
__device__ __forceinline__ void mbar_init(uint32_t a, uint32_t cnt) {
    asm volatile("mbarrier.init.shared.b64 [%0], %1;" :: "r"(a), "r"(cnt) : "memory");
}
__device__ __forceinline__ void mbar_expect(uint32_t a, uint32_t bytes) {
    asm volatile("mbarrier.arrive.expect_tx.shared.b64 _, [%0], %1;"
                 :: "r"(a), "r"(bytes) : "memory");
}
__device__ __forceinline__ void mbar_arrive(uint32_t a) {
    asm volatile("mbarrier.arrive.shared.b64 _, [%0];" :: "r"(a) : "memory");
}
__device__ __forceinline__ void mbar_arrive_cluster(uint32_t a) {
    asm volatile("mbarrier.arrive.shared::cluster.b64 _, [%0];" :: "r"(a) : "memory");
}
__device__ __forceinline__ void mbar_wait(uint32_t a, uint32_t phase) {
    asm volatile(
        "{\n\t.reg .pred P;\n"
        "WLOOP_%=:\n\t"
        "mbarrier.try_wait.parity.acquire.cta.shared::cta.b64 P, [%0], %1, 0x989680;\n\t"
        "@P bra WDONE_%=;\n\t"
        "bra WLOOP_%=;\n"
        "WDONE_%=:\n\t}"
        :: "r"(a), "r"(phase) : "memory");
}
__device__ __forceinline__ void bulk_g2s_mc(uint32_t dst, const void* src,
                                            uint32_t bytes, uint32_t mbar,
                                            uint16_t mask) {
    asm volatile(
        "cp.async.bulk.shared::cluster.global.mbarrier::complete_tx::bytes"
        ".multicast::cluster [%0], [%1], %2, [%3], %4;"
        :: "r"(dst), "l"(src), "r"(bytes), "r"(mbar), "h"(mask) : "memory");
}
__device__ __forceinline__ uint32_t mapa_sh(uint32_t a, uint32_t rank) {
    uint32_t r;
    asm("mapa.shared::cluster.u32 %0, %1, %2;" : "=r"(r) : "r"(a), "r"(rank));
    return r;
}
__device__ __forceinline__ uint32_t ctarank() {
    uint32_t r;
    asm("mov.u32 %0, %%cluster_ctarank;" : "=r"(r));
    return r;
}

// ---------------------------------------------------------------------------
// prep 1: K f32 -> bf16 hi/lo, tile-contiguous + swizzled (seg ^= row&7)
__global__ void split_k_kernel(const float* __restrict__ k) {
    int idx = blockIdx.x * 256 + threadIdx.x;            // one 16B segment each
    const float4* k2 = (const float4*)k;
    float4 fa = k2[idx * 2], fb = k2[idx * 2 + 1];
    uint32_t l0, l1, l2, l3;
    uint32_t h0 = packsplit(fa.x, fa.y, l0);
    uint32_t h1 = packsplit(fa.z, fa.w, l1);
    uint32_t h2 = packsplit(fb.x, fb.y, l2);
    uint32_t h3 = packsplit(fb.z, fb.w, l3);
    int row = idx >> 3, seg = idx & 7;
    int o = row * 8 + (seg ^ (row & 7));                 // uint4 index
    ((uint4*)g_kh)[o] = make_uint4(h0, h1, h2, h3);
    ((uint4*)g_kl)[o] = make_uint4(l0, l1, l2, l3);
}

// prep 2: V f32 [bh][s][d] -> V^T bf16 hi/lo, [bh][t][d][s128] swizzled
__global__ void vt_split_kernel(const float* __restrict__ v) {
    __shared__ float tile[32][33];
    const int bh = blockIdx.z;
    const int d0 = blockIdx.x * 32;
    const int s0 = blockIdx.y * 32;
    const float* vin = v + (size_t)bh * SEQ * DH;
    const int tx = threadIdx.x, ty = threadIdx.y;
#pragma unroll
    for (int j = 0; j < 32; j += 8)
        tile[ty + j][tx] = vin[(size_t)(s0 + ty + j) * DH + (d0 + tx)];
    __syncthreads();
#pragma unroll
    for (int j = 0; j < 32; j += 8) {
        float x = tile[tx][ty + j];
        __nv_bfloat16 h = __float2bfloat16_rn(x);
        __nv_bfloat16 l = __float2bfloat16_rn(x - __bfloat162float(h));
        int d = d0 + ty + j, s = s0 + tx;
        int t = s >> 7, sin = s & 127;
        int seg = (sin >> 3) ^ (d & 7);
        size_t o = ((size_t)(bh * NTILES + t) * DH + d) * KTILE + seg * 8 + (sin & 7);
        g_vth[o] = h;
        g_vtl[o] = l;
    }
}

// ---------------------------------------------------------------------------
// Two-pass, P-free attention with 2-CTA cluster TMA-multicast K/V fills.
__global__ void __launch_bounds__(NTHREADS, 2) __cluster_dims__(2, 1, 1)
attn_mma_kernel(const float* __restrict__ q, const float* __restrict__ v,
                const int* __restrict__ pad,
                float* __restrict__ ctx, float* __restrict__ wout) {
    extern __shared__ char pool[];
    int*   pads = (int*)(pool + OFF_PAD);
    float* Lrow = (float*)(pool + OFF_L);
    float* Crow = (float*)(pool + OFF_C);
    int*   flg  = (int*)(pool + OFF_FLG);
    const uint32_t smem0 = (uint32_t)__cvta_generic_to_shared(pool);
    const uint32_t mbK = smem0 + OFF_MB,      mbV = smem0 + OFF_MB + 8;
    const uint32_t eK  = smem0 + OFF_MB + 16, eV  = smem0 + OFF_MB + 24;

    const int tid  = threadIdx.x;
    const int wid  = tid >> 5;          // 0..7: warp's 16-col k-chunk
    const int lane = tid & 31;
    const int r    = lane >> 2;
    const int tg   = lane & 3;
    const int xr   = lane & 7;          // swizzle xor
    const int sb   = (lane >> 3) & 1;
    const int bh   = blockIdx.y;
    const int qbase = blockIdx.x * ROWS;
    const int b    = bh >> 4;
    const uint32_t rank = ctarank();
    const uint32_t eKp = mapa_sh(eK, rank ^ 1);
    const uint32_t eVp = mapa_sh(eV, rank ^ 1);

    const char* kSrc = (const char*)(rank ? g_kl : g_kh) + (size_t)bh * SEQ * DH * 2;
    const char* vSrc = (const char*)(rank ? g_vtl : g_vth)
                       + (size_t)bh * NTILES * DH * KTILE * 2;
    const uint32_t kDst = smem0 + OFF_K + rank * SZ_KH;
    const uint32_t vDst = smem0 + OFF_V + rank * SZ_VH;

    const int T = (qbase + ROWS - 1) / KTILE + 1;   // causal tile count (pair-uniform)

    if (tid == 0) {
        mbar_init(mbK, 1); mbar_init(mbV, 1);
        mbar_init(eK, 2);  mbar_init(eV, 2);
    }
    __syncthreads();
    asm volatile("barrier.cluster.arrive.aligned;" ::: "memory");

    // ---- phase 0: pads, Lrow, Q load+split ----------------------------------
    {
        if (tid < ROWS) Lrow[tid] = 0.f;
        if (tid == 0) flg[0] = 0;
        const int* pg = pad + b * SEQ;
#pragma unroll
        for (int i = 0; i < 4; ++i) pads[tid + i * NTHREADS] = pg[tid + i * NTHREADS];

        const float* qg = q + ((size_t)bh * SEQ + qbase) * DH;
        int row = tid >> 4, d4 = (tid & 15) * 4;     // 256 thr = 16x16 exactly
        float4 f = *(const float4*)&qg[row * DH + d4];
        uint32_t l0, l1;
        uint32_t h0 = packsplit(f.x, f.y, l0);
        uint32_t h1 = packsplit(f.z, f.w, l1);
        *(uint2*)(pool + OFF_QH + row * QROWB + d4 * 2) = make_uint2(h0, h1);
        *(uint2*)(pool + OFF_QL + row * QROWB + d4 * 2) = make_uint2(l0, l1);
    }
    __syncthreads();

    // ---- Crow (degenerate fill counts) ----------------------------------------
    {
        int row = tid >> 4, ch = tid & 15;
        int qrow = qbase + row;
        int cnt = 0;
        for (int kx = ch * 64; kx < ch * 64 + 64; ++kx) {
            bool pd = pads[kx] != 0;
            cnt += ((kx <= qrow) ? pd : !pd) ? 1 : 0;
        }
        cnt += __shfl_xor_sync(0xffffffffu, cnt, 1);
        cnt += __shfl_xor_sync(0xffffffffu, cnt, 2);
        cnt += __shfl_xor_sync(0xffffffffu, cnt, 4);
        cnt += __shfl_xor_sync(0xffffffffu, cnt, 8);
        if (ch == 0) Crow[row] = (float)cnt;
    }

    // peer mbars initialized from here on
    asm volatile("barrier.cluster.wait.aligned;" ::: "memory");
    if (tid == 0) {                                  // kick K(0), V(0) slices
        mbar_expect(mbK, 2 * SZ_KH);
        bulk_g2s_mc(kDst, kSrc, SZ_KH, mbK, 3);
        mbar_expect(mbV, 2 * SZ_VH);
        bulk_g2s_mc(vDst, vSrc, SZ_VH, mbV, 3);
    }

    // ---- hoist Q a-fragments ----------------------------------------------------
    const uint32_t qA = smem0 + OFF_QH +
        ((lane & 7) + ((lane >> 3) & 1) * 8) * QROWB + ((lane >> 4) & 1) * 16;
    uint32_t qa_h[4][4], qa_l[4][4];
#pragma unroll
    for (int ks = 0; ks < 4; ++ks) {
        ldsm4(qa_h[ks], qA + ks * 32);
        ldsm4(qa_l[ks], qA + ks * 32 + SZ_QROW);
    }

    const int n0 = wid * 16;
    const uint32_t kBase = smem0 + OFF_K +
        (n0 + (lane & 7) + ((lane >> 4) & 1) * 8) * 128;
    const uint32_t vBase = smem0 + OFF_V + (lane & 7) * 256;
    const uint32_t voff = (uint32_t)(((2 * wid + sb) ^ xr) << 4);

    const int qrow0 = qbase + r, qrow1 = qrow0 + 8;
    float lsum0 = 0.f, lsum1 = 0.f;
    int kph = 0, vph = 0, ekph = 0, evph = 0;

    // ======== PASS 1: row sums ====================================================
    for (int t = 0; t < T; ++t) {
        mbar_wait(mbK, kph); kph ^= 1;

        float c0[4] = {0, 0, 0, 0}, c1[4] = {0, 0, 0, 0};
#pragma unroll
        for (int ks = 0; ks < 4; ++ks) {
            uint32_t koff = (uint32_t)(((2 * ks + sb) ^ xr) << 4);
            uint32_t kh[4], kl[4];
            ldsm4(kh, kBase + koff);
            ldsm4(kl, kBase + koff + SZ_KH);
            mma16816(c0, qa_h[ks], kh[0], kh[1]);
            mma16816(c0, qa_h[ks], kl[0], kl[1]);
            mma16816(c0, qa_l[ks], kh[0], kh[1]);
            mma16816(c1, qa_h[ks], kh[2], kh[3]);
            mma16816(c1, qa_h[ks], kl[2], kl[3]);
            mma16816(c1, qa_l[ks], kh[2], kh[3]);
        }
        int colb = t * KTILE + n0 + tg * 2;
#pragma unroll
        for (int nt = 0; nt < 2; ++nt) {
            float* cc = nt ? c1 : c0;
            int cb = colb + nt * 8;
            lsum0 += epival(cc[0], cb,     qrow0, pads)
                   + epival(cc[1], cb + 1, qrow0, pads);
            lsum1 += epival(cc[2], cb,     qrow1, pads)
                   + epival(cc[3], cb + 1, qrow1, pads);
        }
        __syncthreads();                 // all K reads done (this CTA)
        if (tid == 0) {
            mbar_arrive(eK);
            mbar_arrive_cluster(eKp);
            mbar_wait(eK, ekph); ekph ^= 1;      // both CTAs done reading
            int tile = (t + 1 < T) ? t + 1 : 0;  // last refill = K(0) for pass 2
            mbar_expect(mbK, 2 * SZ_KH);
            bulk_g2s_mc(kDst, kSrc + (size_t)tile * SZ_KH, SZ_KH, mbK, 3);
        }
    }

    // ---- Lrow reduction + degenerate flag ----------------------------------------
    lsum0 += __shfl_xor_sync(0xffffffffu, lsum0, 1);
    lsum0 += __shfl_xor_sync(0xffffffffu, lsum0, 2);
    lsum1 += __shfl_xor_sync(0xffffffffu, lsum1, 1);
    lsum1 += __shfl_xor_sync(0xffffffffu, lsum1, 2);
    if (tg == 0) {
        atomicAdd(&Lrow[r], lsum0);
        atomicAdd(&Lrow[r + 8], lsum1);
    }
    __syncthreads();
    if (tid < ROWS && Lrow[tid] == 0.f) flg[0] = 1;
    __syncthreads();

    const float l0 = Lrow[r], l1 = Lrow[r + 8];
    const bool  dg0 = (l0 == 0.f), dg1 = (l1 == 0.f);
    const float inv0 = 1.f / l0, inv1 = 1.f / l1;
    const float fl0 = 1.f / Crow[r], fl1 = 1.f / Crow[r + 8];
    const bool anyd = (flg[0] != 0);

    // ---- W tail fill (cols >= T*128): zeros, or fill pattern for degen rows -----
    for (int tt = T; tt < NTILES; ++tt) {
        for (int j = tid; j < 512; j += NTHREADS) {
            int row = j >> 5, seg = j & 31;
            float4 z = make_float4(0.f, 0.f, 0.f, 0.f);
            if (anyd && Lrow[row] == 0.f) {        // future cols: sel = !pad
                float fl = 1.f / Crow[row];
                int c0 = tt * KTILE + seg * 4;
                z.x = pads[c0]     ? 0.f : fl;
                z.y = pads[c0 + 1] ? 0.f : fl;
                z.z = pads[c0 + 2] ? 0.f : fl;
                z.w = pads[c0 + 3] ? 0.f : fl;
            }
            *(float4*)&wout[((size_t)bh * SEQ + qbase + row) * SEQ
                            + tt * KTILE + seg * 4] = z;
        }
    }

    float oc[8][4] = {};
    float* wr0 = wout + ((size_t)bh * SEQ + qrow0) * SEQ;
    float* wr1 = wout + ((size_t)bh * SEQ + qrow1) * SEQ;

    // ======== PASS 2: recompute, normalize, store W, PV ===========================
    for (int t = 0; t < T; ++t) {
        mbar_wait(mbK, kph); kph ^= 1;

        float c0[4] = {0, 0, 0, 0}, c1[4] = {0, 0, 0, 0};
#pragma unroll
        for (int ks = 0; ks < 4; ++ks) {
            uint32_t koff = (uint32_t)(((2 * ks + sb) ^ xr) << 4);
            uint32_t kh[4], kl[4];
            ldsm4(kh, kBase + koff);
            ldsm4(kl, kBase + koff + SZ_KH);
            mma16816(c0, qa_h[ks], kh[0], kh[1]);
            mma16816(c0, qa_h[ks], kl[0], kl[1]);
            mma16816(c0, qa_l[ks], kh[0], kh[1]);
            mma16816(c1, qa_h[ks], kh[2], kh[3]);
            mma16816(c1, qa_h[ks], kl[2], kl[3]);
            mma16816(c1, qa_l[ks], kh[2], kh[3]);
        }

        uint32_t ah[4], al[4];
        int colb = t * KTILE + n0 + tg * 2;
#pragma unroll
        for (int nt = 0; nt < 2; ++nt) {
            float* cc = nt ? c1 : c0;
            int cb = colb + nt * 8;
            float e0 = epival(cc[0], cb,     qrow0, pads);
            float e1 = epival(cc[1], cb + 1, qrow0, pads);
            float e2 = epival(cc[2], cb,     qrow1, pads);
            float e3 = epival(cc[3], cb + 1, qrow1, pads);
            float w0, w1, w2, w3;
            if (dg0) {
                bool p0 = pads[cb] != 0, p1 = pads[cb + 1] != 0;
                w0 = ((cb     <= qrow0) ? p0 : !p0) ? fl0 : 0.f;
                w1 = ((cb + 1 <= qrow0) ? p1 : !p1) ? fl0 : 0.f;
            } else { w0 = e0 * inv0; w1 = e1 * inv0; }
            if (dg1) {
                bool p0 = pads[cb] != 0, p1 = pads[cb + 1] != 0;
                w2 = ((cb     <= qrow1) ? p0 : !p0) ? fl1 : 0.f;
                w3 = ((cb + 1 <= qrow1) ? p1 : !p1) ? fl1 : 0.f;
            } else { w2 = e2 * inv1; w3 = e3 * inv1; }
            *(float2*)&wr0[cb] = make_float2(w0, w1);
            *(float2*)&wr1[cb] = make_float2(w2, w3);
            ah[nt * 2]     = packsplit(w0, w1, al[nt * 2]);
            ah[nt * 2 + 1] = packsplit(w2, w3, al[nt * 2 + 1]);
        }
        __syncthreads();                 // K reads done
        if (tid == 0) {
            mbar_arrive(eK);
            mbar_arrive_cluster(eKp);
            if (t + 1 < T) {
                mbar_wait(eK, ekph); ekph ^= 1;
                mbar_expect(mbK, 2 * SZ_KH);
                bulk_g2s_mc(kDst, kSrc + (size_t)(t + 1) * SZ_KH, SZ_KH, mbK, 3);
            }
        }

        mbar_wait(mbV, vph); vph ^= 1;
#pragma unroll
        for (int nb = 0; nb < 8; ++nb) {
            uint32_t bh0, bh1, bl0, bl1;
            ldsm2(bh0, bh1, vBase + nb * 2048 + voff);
            ldsm2(bl0, bl1, vBase + nb * 2048 + voff + SZ_VH);
            mma16816(oc[nb], ah, bh0, bh1);
            mma16816(oc[nb], ah, bl0, bl1);
            mma16816(oc[nb], al, bh0, bh1);
        }
        __syncthreads();                 // V reads done
        if (tid == 0) {
            mbar_arrive(eV);
            mbar_arrive_cluster(eVp);
            if (t + 1 < T) {
                mbar_wait(eV, evph); evph ^= 1;
                mbar_expect(mbV, 2 * SZ_VH);
                bulk_g2s_mc(vDst, vSrc + (size_t)(t + 1) * SZ_VH, SZ_VH, mbV, 3);
            }
        }
    }
    __syncthreads();

    // ---- cross-warp k-chunk reduction (K area is free; no more fills) ------------
    {
        char* base = pool + OFF_K + wid * 4096 + lane * 4;
#pragma unroll
        for (int nb = 0; nb < 8; ++nb)
#pragma unroll
            for (int i = 0; i < 4; ++i)
                *(float*)(base + (nb * 4 + i) * 128) = oc[nb][i];
    }
    __syncthreads();
    {
        int vset = tid >> 5;                        // 0..7 -> dim block
        float acc[4] = {0.f, 0.f, 0.f, 0.f};
#pragma unroll
        for (int ww = 0; ww < 8; ++ww) {
            char* bp = pool + OFF_K + ww * 4096 + lane * 4;
#pragma unroll
            for (int i = 0; i < 4; ++i)
                acc[i] += *(float*)(bp + (vset * 4 + i) * 128);
        }
        int rowa = lane >> 2;
        int dim0 = vset * 8 + (lane & 3) * 2;
        // oc accumulated from ALREADY-normalized w -> no 1/L here (round-11 bug)
        float* crow = ctx + ((size_t)bh * SEQ + qbase) * DH;
        *(float2*)&crow[rowa * DH + dim0]       = make_float2(acc[0], acc[1]);
        *(float2*)&crow[(rowa + 8) * DH + dim0] = make_float2(acc[2], acc[3]);
    }

    // ---- degenerate rows: exact ctx via direct masked column-sum of V (rare) ----
    if (anyd) {
        __syncthreads();
        float* part = (float*)(pool + OFF_V);       // scratch 256 floats
        for (int row = 0; row < ROWS; ++row) {
            if (Lrow[row] != 0.f) continue;
            int qrow = qbase + row;
            int d = tid & 63, pt = tid >> 6;
            const float* vg = v + ((size_t)bh * SEQ + pt * 256) * DH + d;
            float s = 0.f;
            for (int k2 = 0; k2 < 256; ++k2) {
                int kk = pt * 256 + k2;
                bool pd = pads[kk] != 0;
                bool sel = (kk <= qrow) ? pd : !pd;
                if (sel) s += vg[(size_t)k2 * DH];
            }
            part[pt * 64 + d] = s;
            __syncthreads();
            if (tid < 64) {
                float tot = part[tid] + part[64 + tid] + part[128 + tid] + part[192 + tid];
                ctx[((size_t)bh * SEQ + qrow) * DH + tid] = tot / Crow[row];
            }
            __syncthreads();
        }
    }

    // no CTA may exit while peer might still remote-arrive on its mbarriers
    asm volatile("barrier.cluster.arrive.aligned;" ::: "memory");
    asm volatile("barrier.cluster.wait.aligned;" ::: "memory");
}

// ---------------------------------------------------------------------------
extern "C" void kernel_launch(void* const* d_in, const int* in_sizes, int n_in,
                              void* d_out, int out_size) {
    (void)in_sizes; (void)n_in;
    const float* q   = (const float*)d_in[0];
    const float* k   = (const float*)d_in[1];
    const float* v   = (const float*)d_in[2];
    const int*   pad = (const int*)d_in[3];

    const long long CTXN = (long long)BH * SEQ * DH;
    const long long WN   = (long long)BH * SEQ * SEQ;

    float* ctxp;
    float* wp;
    if ((long long)out_size >= CTXN + WN) {
        ctxp = (float*)d_out;
        wp   = (float*)d_out + CTXN;
    } else if ((long long)out_size == WN) {
        void* s = nullptr;
        cudaGetSymbolAddress(&s, g_scratch);
        ctxp = (float*)s;
        wp   = (float*)d_out;
    } else {
        void* s = nullptr;
        cudaGetSymbolAddress(&s, g_scratch);
        ctxp = (float*)d_out;
        wp   = (float*)s;
    }

    static bool attr_done = false;
    if (!attr_done) {
        cudaFuncSetAttribute(attn_mma_kernel,
                             cudaFuncAttributeMaxDynamicSharedMemorySize,
                             SMEM_BYTES);
        attr_done = true;
    }

    split_k_kernel<<<(BH * SEQ * DH / 8 + 255) / 256, 256>>>(k);
    dim3 gt(DH / 32, SEQ / 32, BH), bt(32, 8);
    vt_split_kernel<<<gt, bt>>>(v);

    dim3 ga(SEQ / ROWS, BH), ba(NTHREADS);
    attn_mma_kernel<<<ga, ba, SMEM_BYTES>>>(q, v, pad, ctxp, wp);
}

// round 13
// speedup vs baseline: 1.1313x; 1.1313x over previous
#include <cuda_runtime.h>
#include <cuda_bf16.h>
#include <cstdint>

#define BH        64
#define SEQ       1024
#define DH        64
#define ROWS      16
#define NTHREADS  256
#define KTILE     128
#define NTILES    8
#define QROWB     144               // Q smem row bytes (64 bf16 + pad)
#define SZ_KH     16384             // K hi sub-buffer (128 rows x 128B, swizzled)
#define SZ_VH     16384             // V hi sub-buffer (64 rows x 256B, swizzled)

// smem: K 2-stage + V 1-stage pipeline
#define OFF_K0   0                  // stage0: hi 16K | lo 16K
#define OFF_K1   32768              // stage1: hi 16K | lo 16K
#define OFF_V    65536              // hi 16K | lo 16K
#define OFF_QH   98304
#define SZ_QROW  (ROWS * QROWB)     // 2304
#define OFF_QL   (OFF_QH + SZ_QROW) // 100608
#define OFF_PAD  (OFF_QL + SZ_QROW) // 102912
#define OFF_L    (OFF_PAD + SEQ*4)  // 107008
#define OFF_C    (OFF_L + ROWS*4)   // 107072
#define OFF_FLG  (OFF_C + ROWS*4)   // 107136
#define OFF_MB   (OFF_FLG + 16)     // 107152: fK0,fK1,fV,eK0,eK1,eV (8B each)
#define SMEM_BYTES (OFF_MB + 48)    // 107200 (x2 = 214400 <= 227KB)

__device__ __nv_bfloat16 g_kh[(size_t)BH * SEQ * DH];   // tile-contig, swizzled
__device__ __nv_bfloat16 g_kl[(size_t)BH * SEQ * DH];
__device__ __nv_bfloat16 g_vth[(size_t)BH * NTILES * DH * KTILE];  // [bh][t][d][s]
__device__ __nv_bfloat16 g_vtl[(size_t)BH * NTILES * DH * KTILE];
__device__ float g_scratch[(size_t)BH * SEQ * SEQ];

// ---------------------------------------------------------------------------
__device__ __forceinline__ uint32_t packsplit(float x, float y, uint32_t& lo) {
    __nv_bfloat16 hx = __float2bfloat16_rn(x);
    __nv_bfloat16 hy = __float2bfloat16_rn(y);
    __nv_bfloat16 lx = __float2bfloat16_rn(x - __bfloat162float(hx));
    __nv_bfloat16 ly = __float2bfloat16_rn(y - __bfloat162float(hy));
    lo = (uint32_t)__bfloat16_as_ushort(lx) | ((uint32_t)__bfloat16_as_ushort(ly) << 16);
    return (uint32_t)__bfloat16_as_ushort(hx) | ((uint32_t)__bfloat16_as_ushort(hy) << 16);
}

__device__ __forceinline__ void mma16816(float* c, const uint32_t* a,
                                         uint32_t b0, uint32_t b1) {
    asm volatile(
        "mma.sync.aligned.m16n8k16.row.col.f32.bf16.bf16.f32 "
        "{%0,%1,%2,%3},{%4,%5,%6,%7},{%8,%9},{%0,%1,%2,%3};"
        : "+f"(c[0]), "+f"(c[1]), "+f"(c[2]), "+f"(c[3])
        : "r"(a[0]), "r"(a[1]), "r"(a[2]), "r"(a[3]), "r"(b0), "r"(b1));
}

__device__ __forceinline__ void ldsm4(uint32_t* r, uint32_t addr) {
    asm volatile("ldmatrix.sync.aligned.m8n8.x4.shared.b16 {%0,%1,%2,%3},[%4];"
                 : "=r"(r[0]), "=r"(r[1]), "=r"(r[2]), "=r"(r[3]) : "r"(addr));
}
__device__ __forceinline__ void ldsm2(uint32_t& r0, uint32_t& r1, uint32_t addr) {
    asm volatile("ldmatrix.sync.aligned.m8n8.x2.shared.b16 {%0,%1},[%2];"
                 : "=r"(r0), "=r"(r1) : "r"(addr));
}

__device__ __forceinline__ float epival(float s, int col, int qrow, const int* pads) {
    bool m = (pads[col] != 0) || (col > qrow);
    return m ? 0.f : __expf(s * 0.125f);
}

// ---- mbarrier + bulk-copy helpers -------------------------------------------
__device__ __forceinline__ void mbar_init(uint32_t a, uint32_t cnt) {
    asm volatile("mbarrier.init.shared.b64 [%0], %1;" :: "r"(a), "r"(cnt) : "memory");
}
__device__ __forceinline__ void mbar_expect(uint32_t a, uint32_t bytes) {
    asm volatile("mbarrier.arrive.expect_tx.shared.b64 _, [%0], %1;"
                 :: "r"(a), "r"(bytes) : "memory");
}
__device__ __forceinline__ void mbar_arrive(uint32_t a) {
    asm volatile("mbarrier.arrive.shared.b64 _, [%0];" :: "r"(a) : "memory");
}
__device__ __forceinline__ void mbar_wait(uint32_t a, uint32_t phase) {
    asm volatile(
        "{\n\t.reg .pred P;\n"
        "WLOOP_%=:\n\t"
        "mbarrier.try_wait.parity.acquire.cta.shared::cta.b64 P, [%0], %1, 0x989680;\n\t"
        "@P bra WDONE_%=;\n\t"
        "bra WLOOP_%=;\n"
        "WDONE_%=:\n\t}"
        :: "r"(a), "r"(phase) : "memory");
}
__device__ __forceinline__ void bulk_g2s(uint32_t dst, const void* src,
                                         uint32_t bytes, uint32_t mbar) {
    asm volatile(
        "cp.async.bulk.shared::cta.global.mbarrier::complete_tx::bytes "
        "[%0], [%1], %2, [%3];"
        :: "r"(dst), "l"(src), "r"(bytes), "r"(mbar) : "memory");
}

// ---------------------------------------------------------------------------
// prep 1: K f32 -> bf16 hi/lo, tile-contiguous + swizzled (seg ^= row&7)
__global__ void split_k_kernel(const float* __restrict__ k) {
    int idx = blockIdx.x * 256 + threadIdx.x;            // one 16B segment each
    const float4* k2 = (const float4*)k;
    float4 fa = k2[idx * 2], fb = k2[idx * 2 + 1];
    uint32_t l0, l1, l2, l3;
    uint32_t h0 = packsplit(fa.x, fa.y, l0);
    uint32_t h1 = packsplit(fa.z, fa.w, l1);
    uint32_t h2 = packsplit(fb.x, fb.y, l2);
    uint32_t h3 = packsplit(fb.z, fb.w, l3);
    int row = idx >> 3, seg = idx & 7;
    int o = row * 8 + (seg ^ (row & 7));                 // uint4 index
    ((uint4*)g_kh)[o] = make_uint4(h0, h1, h2, h3);
    ((uint4*)g_kl)[o] = make_uint4(l0, l1, l2, l3);
}

// prep 2: V f32 [bh][s][d] -> V^T bf16 hi/lo, [bh][t][d][s128] swizzled
__global__ void vt_split_kernel(const float* __restrict__ v) {
    __shared__ float tile[32][33];
    const int bh = blockIdx.z;
    const int d0 = blockIdx.x * 32;
    const int s0 = blockIdx.y * 32;
    const float* vin = v + (size_t)bh * SEQ * DH;
    const int tx = threadIdx.x, ty = threadIdx.y;
#pragma unroll
    for (int j = 0; j < 32; j += 8)
        tile[ty + j][tx] = vin[(size_t)(s0 + ty + j) * DH + (d0 + tx)];
    __syncthreads();
#pragma unroll
    for (int j = 0; j < 32; j += 8) {
        float x = tile[tx][ty + j];
        __nv_bfloat16 h = __float2bfloat16_rn(x);
        __nv_bfloat16 l = __float2bfloat16_rn(x - __bfloat162float(h));
        int d = d0 + ty + j, s = s0 + tx;
        int t = s >> 7, sin = s & 127;
        int seg = (sin >> 3) ^ (d & 7);
        size_t o = ((size_t)(bh * NTILES + t) * DH + d) * KTILE + seg * 8 + (sin & 7);
        g_vth[o] = h;
        g_vtl[o] = l;
    }
}

// ---------------------------------------------------------------------------
// Two-pass, P-free attention; K double-buffered + V single-buffered mbarrier
// pipeline, NO per-tile __syncthreads (workers only block on 'full' waits).
__global__ __launch_bounds__(NTHREADS, 2)
void attn_mma_kernel(const float* __restrict__ q, const float* __restrict__ v,
                     const int* __restrict__ pad,
                     float* __restrict__ ctx, float* __restrict__ wout) {
    extern __shared__ char pool[];
    int*   pads = (int*)(pool + OFF_PAD);
    float* Lrow = (float*)(pool + OFF_L);
    float* Crow = (float*)(pool + OFF_C);
    int*   flg  = (int*)(pool + OFF_FLG);
    const uint32_t smem0 = (uint32_t)__cvta_generic_to_shared(pool);
    const uint32_t fK0 = smem0 + OFF_MB,      fK1 = smem0 + OFF_MB + 8;
    const uint32_t fV  = smem0 + OFF_MB + 16;
    const uint32_t eK0 = smem0 + OFF_MB + 24, eK1 = smem0 + OFF_MB + 32;
    const uint32_t eV  = smem0 + OFF_MB + 40;

    const int tid  = threadIdx.x;
    const int wid  = tid >> 5;          // 0..7: warp's 16-col k-chunk
    const int lane = tid & 31;
    const int r    = lane >> 2;
    const int tg   = lane & 3;
    const int xr   = lane & 7;          // swizzle xor
    const int sb   = (lane >> 3) & 1;
    const int bh   = blockIdx.y;
    const int qbase = blockIdx.x * ROWS;
    const int b    = bh >> 4;

    const char* khb = (const char*)(g_kh + (size_t)bh * SEQ * DH);
    const char* klb = (const char*)(g_kl + (size_t)bh * SEQ * DH);
    const char* vhb = (const char*)(g_vth + (size_t)bh * NTILES * DH * KTILE);
    const char* vlb = (const char*)(g_vtl + (size_t)bh * NTILES * DH * KTILE);

    const int T = (qbase + ROWS - 1) / KTILE + 1;   // causal tile count
    const int U = 2 * T;                            // total K uses (2 passes)

    if (tid == 0) {
        mbar_init(fK0, 1); mbar_init(fK1, 1); mbar_init(fV, 1);
        mbar_init(eK0, 8); mbar_init(eK1, 8); mbar_init(eV, 8);
    }
    __syncthreads();
    if (tid == 0) {                       // initial fills: K u=0,1 and V(0)
        mbar_expect(fK0, 2 * SZ_KH);
        bulk_g2s(smem0 + OFF_K0,         khb, SZ_KH, fK0);
        bulk_g2s(smem0 + OFF_K0 + SZ_KH, klb, SZ_KH, fK0);
        int t1 = (1 < T) ? 1 : 0;         // u=1 -> tile(1) (pass2 tile0 if T==1)
        mbar_expect(fK1, 2 * SZ_KH);
        bulk_g2s(smem0 + OFF_K1,         khb + (size_t)t1 * SZ_KH, SZ_KH, fK1);
        bulk_g2s(smem0 + OFF_K1 + SZ_KH, klb + (size_t)t1 * SZ_KH, SZ_KH, fK1);
        mbar_expect(fV, 2 * SZ_VH);
        bulk_g2s(smem0 + OFF_V,          vhb, SZ_VH, fV);
        bulk_g2s(smem0 + OFF_V + SZ_VH,  vlb, SZ_VH, fV);
    }

    // ---- phase 0: pads, Lrow, Q load+split ----------------------------------
    {
        if (tid < ROWS) Lrow[tid] = 0.f;
        if (tid == 0) flg[0] = 0;
        const int* pg = pad + b * SEQ;
#pragma unroll
        for (int i = 0; i < 4; ++i) pads[tid + i * NTHREADS] = pg[tid + i * NTHREADS];

        const float* qg = q + ((size_t)bh * SEQ + qbase) * DH;
        int row = tid >> 4, d4 = (tid & 15) * 4;     // 256 thr = 16x16 exactly
        float4 f = *(const float4*)&qg[row * DH + d4];
        uint32_t l0, l1;
        uint32_t h0 = packsplit(f.x, f.y, l0);
        uint32_t h1 = packsplit(f.z, f.w, l1);
        *(uint2*)(pool + OFF_QH + row * QROWB + d4 * 2) = make_uint2(h0, h1);
        *(uint2*)(pool + OFF_QL + row * QROWB + d4 * 2) = make_uint2(l0, l1);
    }
    __syncthreads();

    // ---- Crow (degenerate fill counts) ---------------------------------------
    {
        int row = tid >> 4, ch = tid & 15;
        int qrow = qbase + row;
        int cnt = 0;
        for (int kx = ch * 64; kx < ch * 64 + 64; ++kx) {
            bool pd = pads[kx] != 0;
            cnt += ((kx <= qrow) ? pd : !pd) ? 1 : 0;
        }
        cnt += __shfl_xor_sync(0xffffffffu, cnt, 1);
        cnt += __shfl_xor_sync(0xffffffffu, cnt, 2);
        cnt += __shfl_xor_sync(0xffffffffu, cnt, 4);
        cnt += __shfl_xor_sync(0xffffffffu, cnt, 8);
        if (ch == 0) Crow[row] = (float)cnt;
    }

    // ---- hoist Q a-fragments ---------------------------------------------------
    const uint32_t qA = smem0 + OFF_QH +
        ((lane & 7) + ((lane >> 3) & 1) * 8) * QROWB + ((lane >> 4) & 1) * 16;
    uint32_t qa_h[4][4], qa_l[4][4];
#pragma unroll
    for (int ks = 0; ks < 4; ++ks) {
        ldsm4(qa_h[ks], qA + ks * 32);
        ldsm4(qa_l[ks], qA + ks * 32 + SZ_QROW);
    }

    const int n0 = wid * 16;
    const uint32_t kRel = (n0 + (lane & 7) + ((lane >> 4) & 1) * 8) * 128;
    const uint32_t vBase = smem0 + OFF_V + (lane & 7) * 256;
    const uint32_t voff = (uint32_t)(((2 * wid + sb) ^ xr) << 4);

    const int qrow0 = qbase + r, qrow1 = qrow0 + 8;
    float lsum0 = 0.f, lsum1 = 0.f;

    // ======== PASS 1: row sums (pipelined, no syncthreads) ======================
    for (int t = 0; t < T; ++t) {
        const int u = t, s = u & 1, ph = (u >> 1) & 1;
        const uint32_t kb = smem0 + (s ? OFF_K1 : OFF_K0);
        const uint32_t fKs = s ? fK1 : fK0, eKs = s ? eK1 : eK0;
        mbar_wait(fKs, ph);

        float c0[4] = {0, 0, 0, 0}, c1[4] = {0, 0, 0, 0};
#pragma unroll
        for (int ks = 0; ks < 4; ++ks) {
            uint32_t koff = (uint32_t)(((2 * ks + sb) ^ xr) << 4);
            uint32_t kh[4], kl[4];
            ldsm4(kh, kb + kRel + koff);
            ldsm4(kl, kb + kRel + koff + SZ_KH);
            mma16816(c0, qa_h[ks], kh[0], kh[1]);
            mma16816(c0, qa_h[ks], kl[0], kl[1]);
            mma16816(c0, qa_l[ks], kh[0], kh[1]);
            mma16816(c1, qa_h[ks], kh[2], kh[3]);
            mma16816(c1, qa_h[ks], kl[2], kl[3]);
            mma16816(c1, qa_l[ks], kh[2], kh[3]);
        }
        if (lane == 0) mbar_arrive(eKs);          // K(s) reads done (this warp)
        if (tid == 0 && u + 2 < U) {              // refill stage s for u+2
            mbar_wait(eKs, ph);
            int tile = (u + 2 < T) ? u + 2 : u + 2 - T;
            mbar_expect(fKs, 2 * SZ_KH);
            bulk_g2s(kb,         khb + (size_t)tile * SZ_KH, SZ_KH, fKs);
            bulk_g2s(kb + SZ_KH, klb + (size_t)tile * SZ_KH, SZ_KH, fKs);
        }

        int colb = t * KTILE + n0 + tg * 2;
#pragma unroll
        for (int nt = 0; nt < 2; ++nt) {
            float* cc = nt ? c1 : c0;
            int cb = colb + nt * 8;
            lsum0 += epival(cc[0], cb,     qrow0, pads)
                   + epival(cc[1], cb + 1, qrow0, pads);
            lsum1 += epival(cc[2], cb,     qrow1, pads)
                   + epival(cc[3], cb + 1, qrow1, pads);
        }
    }

    // ---- Lrow reduction + degenerate flag ----------------------------------------
    lsum0 += __shfl_xor_sync(0xffffffffu, lsum0, 1);
    lsum0 += __shfl_xor_sync(0xffffffffu, lsum0, 2);
    lsum1 += __shfl_xor_sync(0xffffffffu, lsum1, 1);
    lsum1 += __shfl_xor_sync(0xffffffffu, lsum1, 2);
    if (tg == 0) {
        atomicAdd(&Lrow[r], lsum0);
        atomicAdd(&Lrow[r + 8], lsum1);
    }
    __syncthreads();
    if (tid < ROWS && Lrow[tid] == 0.f) flg[0] = 1;
    __syncthreads();

    const float l0 = Lrow[r], l1 = Lrow[r + 8];
    const bool  dg0 = (l0 == 0.f), dg1 = (l1 == 0.f);
    const float inv0 = 1.f / l0, inv1 = 1.f / l1;
    const float fl0 = 1.f / Crow[r], fl1 = 1.f / Crow[r + 8];
    const bool anyd = (flg[0] != 0);

    // ---- W tail fill (cols >= T*128): zeros, or fill pattern for degen rows -----
    for (int tt = T; tt < NTILES; ++tt) {
        for (int j = tid; j < 512; j += NTHREADS) {
            int row = j >> 5, seg = j & 31;
            float4 z = make_float4(0.f, 0.f, 0.f, 0.f);
            if (anyd && Lrow[row] == 0.f) {        // future cols: sel = !pad
                float fl = 1.f / Crow[row];
                int c0 = tt * KTILE + seg * 4;
                z.x = pads[c0]     ? 0.f : fl;
                z.y = pads[c0 + 1] ? 0.f : fl;
                z.z = pads[c0 + 2] ? 0.f : fl;
                z.w = pads[c0 + 3] ? 0.f : fl;
            }
            *(float4*)&wout[((size_t)bh * SEQ + qbase + row) * SEQ
                            + tt * KTILE + seg * 4] = z;
        }
    }

    float oc[8][4] = {};
    float* wr0 = wout + ((size_t)bh * SEQ + qrow0) * SEQ;
    float* wr1 = wout + ((size_t)bh * SEQ + qrow1) * SEQ;

    // ======== PASS 2: recompute, normalize, store W, PV (pipelined) ==============
    for (int t = 0; t < T; ++t) {
        const int u = T + t, s = u & 1, ph = (u >> 1) & 1;
        const uint32_t kb = smem0 + (s ? OFF_K1 : OFF_K0);
        const uint32_t fKs = s ? fK1 : fK0, eKs = s ? eK1 : eK0;
        mbar_wait(fKs, ph);

        float c0[4] = {0, 0, 0, 0}, c1[4] = {0, 0, 0, 0};
#pragma unroll
        for (int ks = 0; ks < 4; ++ks) {
            uint32_t koff = (uint32_t)(((2 * ks + sb) ^ xr) << 4);
            uint32_t kh[4], kl[4];
            ldsm4(kh, kb + kRel + koff);
            ldsm4(kl, kb + kRel + koff + SZ_KH);
            mma16816(c0, qa_h[ks], kh[0], kh[1]);
            mma16816(c0, qa_h[ks], kl[0], kl[1]);
            mma16816(c0, qa_l[ks], kh[0], kh[1]);
            mma16816(c1, qa_h[ks], kh[2], kh[3]);
            mma16816(c1, qa_h[ks], kl[2], kl[3]);
            mma16816(c1, qa_l[ks], kh[2], kh[3]);
        }
        if (lane == 0) mbar_arrive(eKs);
        if (tid == 0 && u + 2 < U) {
            mbar_wait(eKs, ph);
            int tile = u + 2 - T;                 // u+2 >= T always here
            mbar_expect(fKs, 2 * SZ_KH);
            bulk_g2s(kb,         khb + (size_t)tile * SZ_KH, SZ_KH, fKs);
            bulk_g2s(kb + SZ_KH, klb + (size_t)tile * SZ_KH, SZ_KH, fKs);
        }

        uint32_t ah[4], al[4];
        int colb = t * KTILE + n0 + tg * 2;
#pragma unroll
        for (int nt = 0; nt < 2; ++nt) {
            float* cc = nt ? c1 : c0;
            int cb = colb + nt * 8;
            float e0 = epival(cc[0], cb,     qrow0, pads);
            float e1 = epival(cc[1], cb + 1, qrow0, pads);
            float e2 = epival(cc[2], cb,     qrow1, pads);
            float e3 = epival(cc[3], cb + 1, qrow1, pads);
            float w0, w1, w2, w3;
            if (dg0) {
                bool p0 = pads[cb] != 0, p1 = pads[cb + 1] != 0;
                w0 = ((cb     <= qrow0) ? p0 : !p0) ? fl0 : 0.f;
                w1 = ((cb + 1 <= qrow0) ? p1 : !p1) ? fl0 : 0.f;
            } else { w0 = e0 * inv0; w1 = e1 * inv0; }
            if (dg1) {
                bool p0 = pads[cb] != 0, p1 = pads[cb + 1] != 0;
                w2 = ((cb     <= qrow1) ? p0 : !p0) ? fl1 : 0.f;
                w3 = ((cb + 1 <= qrow1) ? p1 : !p1) ? fl1 : 0.f;
            } else { w2 = e2 * inv1; w3 = e3 * inv1; }
            *(float2*)&wr0[cb] = make_float2(w0, w1);
            *(float2*)&wr1[cb] = make_float2(w2, w3);
            ah[nt * 2]     = packsplit(w0, w1, al[nt * 2]);
            ah[nt * 2 + 1] = packsplit(w2, w3, al[nt * 2 + 1]);
        }

        const int vph = t & 1;
        mbar_wait(fV, vph);
#pragma unroll
        for (int nb = 0; nb < 8; ++nb) {
            uint32_t bh0, bh1, bl0, bl1;
            ldsm2(bh0, bh1, vBase + nb * 2048 + voff);
            ldsm2(bl0, bl1, vBase + nb * 2048 + voff + SZ_VH);
            mma16816(oc[nb], ah, bh0, bh1);
            mma16816(oc[nb], ah, bl0, bl1);
            mma16816(oc[nb], al, bh0, bh1);
        }
        if (lane == 0) mbar_arrive(eV);
        if (tid == 0 && t + 1 < T) {
            mbar_wait(eV, vph);
            mbar_expect(fV, 2 * SZ_VH);
            bulk_g2s(smem0 + OFF_V,         vhb + (size_t)(t + 1) * SZ_VH, SZ_VH, fV);
            bulk_g2s(smem0 + OFF_V + SZ_VH, vlb + (size_t)(t + 1) * SZ_VH, SZ_VH, fV);
        }
    }
    __syncthreads();                     // pipeline drained; buffers reusable

    // ---- cross-warp k-chunk reduction (stage-0 area as scratch) ----------------
    {
        char* base = pool + OFF_K0 + wid * 4096 + lane * 4;
#pragma unroll
        for (int nb = 0; nb < 8; ++nb)
#pragma unroll
            for (int i = 0; i < 4; ++i)
                *(float*)(base + (nb * 4 + i) * 128) = oc[nb][i];
    }
    __syncthreads();
    {
        int vset = tid >> 5;                        // 0..7 -> dim block
        float acc[4] = {0.f, 0.f, 0.f, 0.f};
#pragma unroll
        for (int ww = 0; ww < 8; ++ww) {
            char* bp = pool + OFF_K0 + ww * 4096 + lane * 4;
#pragma unroll
            for (int i = 0; i < 4; ++i)
                acc[i] += *(float*)(bp + (vset * 4 + i) * 128);
        }
        int rowa = lane >> 2;
        int dim0 = vset * 8 + (lane & 3) * 2;
        // w already normalized -> write acc directly (NO 1/L here)
        float* crow = ctx + ((size_t)bh * SEQ + qbase) * DH;
        *(float2*)&crow[rowa * DH + dim0]       = make_float2(acc[0], acc[1]);
        *(float2*)&crow[(rowa + 8) * DH + dim0] = make_float2(acc[2], acc[3]);
    }

    // ---- degenerate rows: exact ctx via direct masked column-sum of V (rare) ----
    if (anyd) {
        __syncthreads();
        float* part = (float*)(pool + OFF_V);       // scratch 256 floats
        for (int row = 0; row < ROWS; ++row) {
            if (Lrow[row] != 0.f) continue;
            int qrow = qbase + row;
            int d = tid & 63, pt = tid >> 6;
            const float* vg = v + ((size_t)bh * SEQ + pt * 256) * DH + d;
            float s2 = 0.f;
            for (int k2 = 0; k2 < 256; ++k2) {
                int kk = pt * 256 + k2;
                bool pd = pads[kk] != 0;
                bool sel = (kk <= qrow) ? pd : !pd;
                if (sel) s2 += vg[(size_t)k2 * DH];
            }
            part[pt * 64 + d] = s2;
            __syncthreads();
            if (tid < 64) {
                float tot = part[tid] + part[64 + tid] + part[128 + tid] + part[192 + tid];
                ctx[((size_t)bh * SEQ + qrow) * DH + tid] = tot / Crow[row];
            }
            __syncthreads();
        }
    }
}

// ---------------------------------------------------------------------------
extern "C" void kernel_launch(void* const* d_in, const int* in_sizes, int n_in,
                              void* d_out, int out_size) {
    (void)in_sizes; (void)n_in;
    const float* q   = (const float*)d_in[0];
    const float* k   = (const float*)d_in[1];
    const float* v   = (const float*)d_in[2];
    const int*   pad = (const int*)d_in[3];

    const long long CTXN = (long long)BH * SEQ * DH;
    const long long WN   = (long long)BH * SEQ * SEQ;

    float* ctxp;
    float* wp;
    if ((long long)out_size >= CTXN + WN) {
        ctxp = (float*)d_out;
        wp   = (float*)d_out + CTXN;
    } else if ((long long)out_size == WN) {
        void* s = nullptr;
        cudaGetSymbolAddress(&s, g_scratch);
        ctxp = (float*)s;
        wp   = (float*)d_out;
    } else {
        void* s = nullptr;
        cudaGetSymbolAddress(&s, g_scratch);
        ctxp = (float*)d_out;
        wp   = (float*)s;
    }

    static bool attr_done = false;
    if (!attr_done) {
        cudaFuncSetAttribute(attn_mma_kernel,
                             cudaFuncAttributeMaxDynamicSharedMemorySize,
                             SMEM_BYTES);
        attr_done = true;
    }

    split_k_kernel<<<(BH * SEQ * DH / 8 + 255) / 256, 256>>>(k);
    dim3 gt(DH / 32, SEQ / 32, BH), bt(32, 8);
    vt_split_kernel<<<gt, bt>>>(v);

    dim3 ga(SEQ / ROWS, BH), ba(NTHREADS);
    attn_mma_kernel<<<ga, ba, SMEM_BYTES>>>(q, v, pad, ctxp, wp);
}